// round 2
// baseline (speedup 1.0000x reference)
#include <cuda_runtime.h>
#include <cstdint>

#define B_   4
#define N_   2048
#define DIN  128
#define H_   4
#define HD_  32
#define LOG2E 1.4426950408889634f

// ---------------- scratch (no allocs allowed) ----------------
__device__ float    g_h [B_ * N_ * DIN];     // 4 MB
__device__ float    g_ei[B_ * N_ * H_];      // pre-scaled by log2e
__device__ float    g_ej[B_ * N_ * H_];
__device__ unsigned g_adjw[(N_ / 32) * N_];  // [jw][i]  512 KB, transposed bitmask

__device__ __forceinline__ float ex2f(float x) {
    float r;
    asm("ex2.approx.ftz.f32 %0, %1;" : "=f"(r) : "f"(x));
    return r;
}

// ---------------- kernel 1: h = x @ W^T (8192x128x128) ----------------
#define WT_STRIDE 132   // multiple of 4 -> float4-aligned rows; 132%32=4 -> conflict-free
#define GEMM_SMEM ((128 * WT_STRIDE + 64 * 128) * 4)
__global__ void k_gemm(const float* __restrict__ x, const float* __restrict__ W) {
    extern __shared__ float sm[];
    float* Wt = sm;                     // [128][WT_STRIDE]  W transposed
    float* xs = sm + 128 * WT_STRIDE;   // [64][128]
    const int t    = threadIdx.x;
    const int row0 = blockIdx.x * 64;

    for (int idx = t; idx < 128 * 128; idx += 256) {
        int c = idx >> 7, k = idx & 127;
        Wt[k * WT_STRIDE + c] = W[idx];
    }
    for (int idx = t; idx < 64 * 128 / 4; idx += 256) {
        *(float4*)&xs[idx * 4] = *(const float4*)&x[(size_t)row0 * 128 + idx * 4];
    }
    __syncthreads();

    const int rg = t >> 5, cg = t & 31;   // 8 rows x 4 cols per thread
    float acc[8][4];
    #pragma unroll
    for (int r = 0; r < 8; r++)
        #pragma unroll
        for (int c = 0; c < 4; c++) acc[r][c] = 0.f;

    #pragma unroll 4
    for (int k = 0; k < 128; k++) {
        float4 wv = *(const float4*)&Wt[k * WT_STRIDE + cg * 4];
        #pragma unroll
        for (int r = 0; r < 8; r++) {
            float xv = xs[(rg * 8 + r) * 128 + k];
            acc[r][0] = fmaf(xv, wv.x, acc[r][0]);
            acc[r][1] = fmaf(xv, wv.y, acc[r][1]);
            acc[r][2] = fmaf(xv, wv.z, acc[r][2]);
            acc[r][3] = fmaf(xv, wv.w, acc[r][3]);
        }
    }
    #pragma unroll
    for (int r = 0; r < 8; r++) {
        *(float4*)&g_h[(size_t)(row0 + rg * 8 + r) * 128 + cg * 4] =
            make_float4(acc[r][0], acc[r][1], acc[r][2], acc[r][3]);
    }
}

// ---------------- kernel 1b: ei/ej per (b,n,head), pre-scaled by log2e ----------------
__global__ void k_eij(const float* __restrict__ a) {
    __shared__ float as[2 * H_ * HD_];   // 256 coefficients, pre-scaled
    const int t = threadIdx.x;
    if (t < 256) as[t] = a[t] * LOG2E;
    __syncthreads();

    const int warp = t >> 5, lane = t & 31;
    const int row  = blockIdx.x * 8 + warp;          // flat (b*N + n)
    float4 hv = *(const float4*)&g_h[(size_t)row * 128 + lane * 4];
    const int hh    = lane >> 3;
    const int dbase = (lane & 7) * 4;
    const float* a1 = &as[hh * 64];
    const float* a2 = &as[hh * 64 + 32];

    float p1 = hv.x * a1[dbase] + hv.y * a1[dbase + 1] + hv.z * a1[dbase + 2] + hv.w * a1[dbase + 3];
    float p2 = hv.x * a2[dbase] + hv.y * a2[dbase + 1] + hv.z * a2[dbase + 2] + hv.w * a2[dbase + 3];
    #pragma unroll
    for (int o = 1; o < 8; o <<= 1) {
        p1 += __shfl_xor_sync(0xffffffffu, p1, o, 8);
        p2 += __shfl_xor_sync(0xffffffffu, p2, o, 8);
    }
    if ((lane & 7) == 0) {
        g_ei[row * H_ + hh] = p1;
        g_ej[row * H_ + hh] = p2;
    }
}

// ---------------- kernel 2: pack adj -> transposed bitmask ----------------
__global__ void k_pack(const int* __restrict__ adj) {
    const int gw   = (blockIdx.x * blockDim.x + threadIdx.x) >> 5;   // global warp
    const int lane = threadIdx.x & 31;
    const int i  = gw >> 6;       // row
    const int jw = gw & 63;       // word within row
    int v = adj[(size_t)i * N_ + jw * 32 + lane];
    unsigned word = __ballot_sync(0xffffffffu, v != 0);
    if (lane == 0) g_adjw[jw * N_ + i] = word;
}

// ---------------- kernel 3: fused masked softmax + aggregation ----------------
// grid (16, H, B), 256 threads. BI = BJ = 128.
#define ATTN_SMEM ((4096 + 16384 + 128 + 512 + 256) * 4)
__global__ void k_attn(float* __restrict__ out) {
    extern __shared__ float sm[];
    float*    hs   = sm;                          // [128][32]   h tile (this head)
    float*    pt   = sm + 4096;                   // [j][i] = exp-weights (transposed)
    float*    ejs  = pt + 16384;                  // [128]
    unsigned* adjs = (unsigned*)(ejs + 128);      // [4][128]
    float*    zsm  = (float*)(adjs + 512);        // [256]

    const int t  = threadIdx.x;
    const int i0 = blockIdx.x * 128;
    const int hh = blockIdx.y;
    const int b  = blockIdx.z;

    // phase-A mapping
    const int iA = t & 127, jg = t >> 7;          // jg in {0,1}: 64 j's each
    const float ei_r = g_ei[(b * N_ + i0 + iA) * H_ + hh];
    float zpart = 0.f;

    // phase-B mapping: rows {2io, 2io+1}, dims dg*8..dg*8+7
    const int io = t & 63, dg = t >> 6;
    unsigned long long acc[2][4];
    #pragma unroll
    for (int r = 0; r < 2; r++)
        #pragma unroll
        for (int k = 0; k < 4; k++) acc[r][k] = 0ull;

    const float* gh_b = g_h + (size_t)b * N_ * DIN + hh * HD_;

    for (int j0 = 0; j0 < N_; j0 += 128) {
        __syncthreads();
        // stage h tile (coalesced float4)
        #pragma unroll
        for (int idx = t; idx < 1024; idx += 256) {
            int j = idx >> 3, d4 = idx & 7;
            *(float4*)&hs[j * 32 + d4 * 4] =
                *(const float4*)&gh_b[(size_t)(j0 + j) * DIN + d4 * 4];
        }
        if (t < 128) ejs[t] = g_ej[(b * N_ + j0 + t) * H_ + hh];
        #pragma unroll
        for (int idx = t; idx < 512; idx += 256) {
            int jwl = idx >> 7, il = idx & 127;
            adjs[jwl * 128 + il] = g_adjw[((j0 >> 5) + jwl) * N_ + i0 + il];
        }
        __syncthreads();

        // ---- phase A: weights + running denominator (no max pass needed: s bounded) ----
        {
            unsigned w0 = adjs[(jg * 2 + 0) * 128 + iA];
            unsigned w1 = adjs[(jg * 2 + 1) * 128 + iA];
            const int jb = jg * 64;
            #pragma unroll 8
            for (int jj = 0; jj < 32; jj++) {
                float s0 = ei_r + ejs[jb + jj];
                s0 = fmaxf(s0, 0.2f * s0);                 // leaky (log2e-scaled domain)
                float e0 = ex2f(s0);
                e0 = ((w0 >> jj) & 1u) ? e0 : 0.f;
                pt[(jb + jj) * 128 + iA] = e0;
                zpart += e0;

                float s1 = ei_r + ejs[jb + 32 + jj];
                s1 = fmaxf(s1, 0.2f * s1);
                float e1 = ex2f(s1);
                e1 = ((w1 >> jj) & 1u) ? e1 : 0.f;
                pt[(jb + 32 + jj) * 128 + iA] = e1;
                zpart += e1;
            }
        }
        __syncthreads();

        // ---- phase B: out[i,d] += P[i,j] * h[j,d] via packed f32x2 FMA ----
        #pragma unroll 4
        for (int j = 0; j < 128; j++) {
            float2 pv = *(const float2*)&pt[j * 128 + 2 * io];
            const float* hrow = &hs[j * 32 + dg * 8];
            ulonglong2 ha = *(const ulonglong2*)(hrow);       // h[d0..d3]
            ulonglong2 hb = *(const ulonglong2*)(hrow + 4);   // h[d4..d7]
            unsigned long long pp0, pp1;
            asm("mov.b64 %0, {%1, %1};" : "=l"(pp0) : "f"(pv.x));
            asm("mov.b64 %0, {%1, %1};" : "=l"(pp1) : "f"(pv.y));
            asm("fma.rn.f32x2 %0, %1, %2, %0;" : "+l"(acc[0][0]) : "l"(pp0), "l"(ha.x));
            asm("fma.rn.f32x2 %0, %1, %2, %0;" : "+l"(acc[0][1]) : "l"(pp0), "l"(ha.y));
            asm("fma.rn.f32x2 %0, %1, %2, %0;" : "+l"(acc[0][2]) : "l"(pp0), "l"(hb.x));
            asm("fma.rn.f32x2 %0, %1, %2, %0;" : "+l"(acc[0][3]) : "l"(pp0), "l"(hb.y));
            asm("fma.rn.f32x2 %0, %1, %2, %0;" : "+l"(acc[1][0]) : "l"(pp1), "l"(ha.x));
            asm("fma.rn.f32x2 %0, %1, %2, %0;" : "+l"(acc[1][1]) : "l"(pp1), "l"(ha.y));
            asm("fma.rn.f32x2 %0, %1, %2, %0;" : "+l"(acc[1][2]) : "l"(pp1), "l"(hb.x));
            asm("fma.rn.f32x2 %0, %1, %2, %0;" : "+l"(acc[1][3]) : "l"(pp1), "l"(hb.y));
        }
    }

    // ---- epilogue: reduce Z, normalize, store ----
    __syncthreads();
    zsm[jg * 128 + iA] = zpart;
    __syncthreads();

    #pragma unroll
    for (int r = 0; r < 2; r++) {
        const int row = 2 * io + r;
        const float zinv = 1.0f / (zsm[row] + zsm[128 + row]);
        float o[8];
        #pragma unroll
        for (int k = 0; k < 4; k++) {
            float2 f = *(float2*)&acc[r][k];
            o[2 * k]     = f.x * zinv;
            o[2 * k + 1] = f.y * zinv;
        }
        float* op = out + ((size_t)(b * N_) + i0 + row) * DIN + hh * HD_ + dg * 8;
        *(float4*)&op[0] = make_float4(o[0], o[1], o[2], o[3]);
        *(float4*)&op[4] = make_float4(o[4], o[5], o[6], o[7]);
    }
}

// ---------------- launch ----------------
extern "C" void kernel_launch(void* const* d_in, const int* in_sizes, int n_in,
                              void* d_out, int out_size) {
    const float* x   = (const float*)d_in[0];
    const int*   adj = (const int*)d_in[1];
    const float* W   = (const float*)d_in[2];
    const float* a   = (const float*)d_in[3];
    float*       out = (float*)d_out;

    cudaFuncSetAttribute(k_gemm, cudaFuncAttributeMaxDynamicSharedMemorySize, GEMM_SMEM);
    cudaFuncSetAttribute(k_attn, cudaFuncAttributeMaxDynamicSharedMemorySize, ATTN_SMEM);

    k_gemm<<<B_ * N_ / 64, 256, GEMM_SMEM>>>(x, W);
    k_eij <<<B_ * N_ / 8, 256>>>(a);
    k_pack<<<(N_ * (N_ / 32) * 32) / 256, 256>>>(adj);
    k_attn<<<dim3(N_ / 128, H_, B_), 256, ATTN_SMEM>>>(out);
}

// round 3
// speedup vs baseline: 1.0820x; 1.0820x over previous
#include <cuda_runtime.h>
#include <cstdint>

#define B_   4
#define N_   2048
#define DIN  128
#define H_   4
#define HD_  32
#define LOG2E 1.4426950408889634f

// ---------------- scratch (no allocs allowed) ----------------
__device__ float    g_h [B_ * N_ * DIN];     // 4 MB
__device__ float    g_ei[B_ * N_ * H_];      // pre-scaled by log2e
__device__ float    g_ej[B_ * N_ * H_];
__device__ unsigned g_adjw[(N_ / 32) * N_];  // [jw][i]  512 KB, transposed bitmask

__device__ __forceinline__ float ex2f(float x) {
    float r;
    asm("ex2.approx.ftz.f32 %0, %1;" : "=f"(r) : "f"(x));
    return r;
}

// ---------------- kernel 1: h = x @ W^T (8192x128x128) ----------------
#define WT_STRIDE 132   // multiple of 4 -> float4-aligned rows; 132%32=4 -> conflict-free
#define GEMM_SMEM ((128 * WT_STRIDE + 64 * 128) * 4)
__global__ void k_gemm(const float* __restrict__ x, const float* __restrict__ W) {
    extern __shared__ float sm[];
    float* Wt = sm;                     // [128][WT_STRIDE]  W transposed
    float* xs = sm + 128 * WT_STRIDE;   // [64][128]
    const int t    = threadIdx.x;
    const int row0 = blockIdx.x * 64;

    for (int idx = t; idx < 128 * 128; idx += 256) {
        int c = idx >> 7, k = idx & 127;
        Wt[k * WT_STRIDE + c] = W[idx];
    }
    for (int idx = t; idx < 64 * 128 / 4; idx += 256) {
        *(float4*)&xs[idx * 4] = *(const float4*)&x[(size_t)row0 * 128 + idx * 4];
    }
    __syncthreads();

    const int rg = t >> 5, cg = t & 31;   // 8 rows x 4 cols per thread
    float acc[8][4];
    #pragma unroll
    for (int r = 0; r < 8; r++)
        #pragma unroll
        for (int c = 0; c < 4; c++) acc[r][c] = 0.f;

    #pragma unroll 4
    for (int k = 0; k < 128; k++) {
        float4 wv = *(const float4*)&Wt[k * WT_STRIDE + cg * 4];
        #pragma unroll
        for (int r = 0; r < 8; r++) {
            float xv = xs[(rg * 8 + r) * 128 + k];
            acc[r][0] = fmaf(xv, wv.x, acc[r][0]);
            acc[r][1] = fmaf(xv, wv.y, acc[r][1]);
            acc[r][2] = fmaf(xv, wv.z, acc[r][2]);
            acc[r][3] = fmaf(xv, wv.w, acc[r][3]);
        }
    }
    #pragma unroll
    for (int r = 0; r < 8; r++) {
        *(float4*)&g_h[(size_t)(row0 + rg * 8 + r) * 128 + cg * 4] =
            make_float4(acc[r][0], acc[r][1], acc[r][2], acc[r][3]);
    }
}

// ---------------- kernel 1b: ei/ej per (b,n,head), pre-scaled by log2e ----------------
__global__ void k_eij(const float* __restrict__ a) {
    __shared__ float as[2 * H_ * HD_];   // 256 coefficients, pre-scaled
    const int t = threadIdx.x;
    if (t < 256) as[t] = a[t] * LOG2E;
    __syncthreads();

    const int warp = t >> 5, lane = t & 31;
    const int row  = blockIdx.x * 8 + warp;          // flat (b*N + n)
    float4 hv = *(const float4*)&g_h[(size_t)row * 128 + lane * 4];
    const int hh    = lane >> 3;
    const int dbase = (lane & 7) * 4;
    const float* a1 = &as[hh * 64];
    const float* a2 = &as[hh * 64 + 32];

    float p1 = hv.x * a1[dbase] + hv.y * a1[dbase + 1] + hv.z * a1[dbase + 2] + hv.w * a1[dbase + 3];
    float p2 = hv.x * a2[dbase] + hv.y * a2[dbase + 1] + hv.z * a2[dbase + 2] + hv.w * a2[dbase + 3];
    #pragma unroll
    for (int o = 1; o < 8; o <<= 1) {
        p1 += __shfl_xor_sync(0xffffffffu, p1, o, 8);
        p2 += __shfl_xor_sync(0xffffffffu, p2, o, 8);
    }
    if ((lane & 7) == 0) {
        g_ei[row * H_ + hh] = p1;
        g_ej[row * H_ + hh] = p2;
    }
}

// ---------------- kernel 2: pack adj -> transposed bitmask ----------------
__global__ void k_pack(const int* __restrict__ adj) {
    const int gw   = (blockIdx.x * blockDim.x + threadIdx.x) >> 5;   // global warp
    const int lane = threadIdx.x & 31;
    const int i  = gw >> 6;       // row
    const int jw = gw & 63;       // word within row
    int v = adj[(size_t)i * N_ + jw * 32 + lane];
    unsigned word = __ballot_sync(0xffffffffu, v != 0);
    if (lane == 0) g_adjw[jw * N_ + i] = word;
}

// ---------------- kernel 3: fused masked softmax + aggregation ----------------
// grid (16, H, B), 256 threads. BI = BJ = 128.
// Phase B: 8i x 8d register tile per thread, 4-way j-split, f32x2 FMAs.
#define ATTN_SMEM ((4096 + 16384 + 128 + 512 + 256) * 4)
__global__ void __launch_bounds__(256) k_attn(float* __restrict__ out) {
    extern __shared__ float sm[];
    float*    hs   = sm;                          // [128][32]   h tile (this head)
    float*    pt   = sm + 4096;                   // [j][i] weights; reused as reduce buf
    float*    ejs  = pt + 16384;                  // [128]
    unsigned* adjs = (unsigned*)(ejs + 128);      // [4][128]
    float*    zsm  = (float*)(adjs + 512);        // [256]

    const int t  = threadIdx.x;
    const int i0 = blockIdx.x * 128;
    const int hh = blockIdx.y;
    const int b  = blockIdx.z;

    // phase-A mapping
    const int iA = t & 127, jg = t >> 7;          // jg in {0,1}: 64 j's each
    const float ei_r = g_ei[(b * N_ + i0 + iA) * H_ + hh];
    float zpart = 0.f;

    // phase-B mapping: jh = quarter of j, slot -> (ig, dg)
    const int jh   = t >> 6;          // 0..3 : j in [jh*32, jh*32+32)
    const int slot = t & 63;
    const int ig   = slot >> 2;       // 0..15 : i = ig*8 .. +8
    const int dg   = slot & 3;        // d = dg*8 .. +8
    unsigned long long acc[4][8];     // [ipair][dd], f32x2 = (i even, i odd)
    #pragma unroll
    for (int r = 0; r < 4; r++)
        #pragma unroll
        for (int k = 0; k < 8; k++) acc[r][k] = 0ull;

    const float* gh_b = g_h + (size_t)b * N_ * DIN + hh * HD_;

    for (int j0 = 0; j0 < N_; j0 += 128) {
        __syncthreads();
        // stage h tile (coalesced float4)
        #pragma unroll
        for (int idx = t; idx < 1024; idx += 256) {
            int j = idx >> 3, d4 = idx & 7;
            *(float4*)&hs[j * 32 + d4 * 4] =
                *(const float4*)&gh_b[(size_t)(j0 + j) * DIN + d4 * 4];
        }
        if (t < 128) ejs[t] = g_ej[(b * N_ + j0 + t) * H_ + hh];
        #pragma unroll
        for (int idx = t; idx < 512; idx += 256) {
            int jwl = idx >> 7, il = idx & 127;
            adjs[jwl * 128 + il] = g_adjw[((j0 >> 5) + jwl) * N_ + i0 + il];
        }
        __syncthreads();

        // ---- phase A: weights + running denominator (scores bounded: no max pass) ----
        {
            unsigned w0 = adjs[(jg * 2 + 0) * 128 + iA];
            unsigned w1 = adjs[(jg * 2 + 1) * 128 + iA];
            const int jb = jg * 64;
            #pragma unroll 8
            for (int jj = 0; jj < 32; jj++) {
                float s0 = ei_r + ejs[jb + jj];
                s0 = fmaxf(s0, 0.2f * s0);                 // leaky (log2e-scaled domain)
                float e0 = ex2f(s0);
                e0 = ((w0 >> jj) & 1u) ? e0 : 0.f;
                pt[(jb + jj) * 128 + iA] = e0;
                zpart += e0;

                float s1 = ei_r + ejs[jb + 32 + jj];
                s1 = fmaxf(s1, 0.2f * s1);
                float e1 = ex2f(s1);
                e1 = ((w1 >> jj) & 1u) ? e1 : 0.f;
                pt[(jb + 32 + jj) * 128 + iA] = e1;
                zpart += e1;
            }
        }
        __syncthreads();

        // ---- phase B: acc[i,d] += P[i,j] * h[j,d], 8x8 tile, f32x2 ----
        #pragma unroll 4
        for (int jj = 0; jj < 32; jj++) {
            const int j = jh * 32 + jj;
            const float* prow = &pt[j * 128 + ig * 8];
            ulonglong2 pa = *(const ulonglong2*)prow;         // i-pairs 0,1
            ulonglong2 pb = *(const ulonglong2*)(prow + 4);   // i-pairs 2,3
            const float* hrow = &hs[j * 32 + dg * 8];
            float4 h0 = *(const float4*)hrow;
            float4 h1 = *(const float4*)(hrow + 4);
            unsigned long long hv[8];
            asm("mov.b64 %0, {%1, %1};" : "=l"(hv[0]) : "f"(h0.x));
            asm("mov.b64 %0, {%1, %1};" : "=l"(hv[1]) : "f"(h0.y));
            asm("mov.b64 %0, {%1, %1};" : "=l"(hv[2]) : "f"(h0.z));
            asm("mov.b64 %0, {%1, %1};" : "=l"(hv[3]) : "f"(h0.w));
            asm("mov.b64 %0, {%1, %1};" : "=l"(hv[4]) : "f"(h1.x));
            asm("mov.b64 %0, {%1, %1};" : "=l"(hv[5]) : "f"(h1.y));
            asm("mov.b64 %0, {%1, %1};" : "=l"(hv[6]) : "f"(h1.z));
            asm("mov.b64 %0, {%1, %1};" : "=l"(hv[7]) : "f"(h1.w));
            #pragma unroll
            for (int k = 0; k < 8; k++) {
                asm("fma.rn.f32x2 %0, %1, %2, %0;" : "+l"(acc[0][k]) : "l"(pa.x), "l"(hv[k]));
                asm("fma.rn.f32x2 %0, %1, %2, %0;" : "+l"(acc[1][k]) : "l"(pa.y), "l"(hv[k]));
                asm("fma.rn.f32x2 %0, %1, %2, %0;" : "+l"(acc[2][k]) : "l"(pb.x), "l"(hv[k]));
                asm("fma.rn.f32x2 %0, %1, %2, %0;" : "+l"(acc[3][k]) : "l"(pb.y), "l"(hv[k]));
            }
        }
    }

    // ---- epilogue: write partials (conflict-free interleave), reduce, normalize ----
    __syncthreads();
    zsm[jg * 128 + iA] = zpart;
    float2* buf = (float2*)pt;   // 8192 float2 slots
    #pragma unroll
    for (int ip = 0; ip < 4; ip++)
        #pragma unroll
        for (int dd = 0; dd < 8; dd++)
            buf[(ip * 8 + dd) * 256 + t] = *(float2*)&acc[ip][dd];
    __syncthreads();

    // reader: thread t -> i-pair = t>>2 (rows 2p, 2p+1), d block = (t&3)*8
    {
        const int ipair = t >> 2;
        const int dq    = t & 3;
        const int i_e   = 2 * ipair;
        const float zinv0 = 1.0f / (zsm[i_e]     + zsm[128 + i_e]);
        const float zinv1 = 1.0f / (zsm[i_e + 1] + zsm[129 + i_e]);
        const int owner = (ipair >> 2) * 4 + dq;     // slot that produced it
        const int kbase = (ipair & 3) * 8;
        float o0[8], o1[8];
        #pragma unroll
        for (int dd = 0; dd < 8; dd++) {
            float2 s = buf[(kbase + dd) * 256 + 0 * 64 + owner];
            float2 s1 = buf[(kbase + dd) * 256 + 1 * 64 + owner];
            float2 s2 = buf[(kbase + dd) * 256 + 2 * 64 + owner];
            float2 s3 = buf[(kbase + dd) * 256 + 3 * 64 + owner];
            float sx = s.x + s1.x + s2.x + s3.x;
            float sy = s.y + s1.y + s2.y + s3.y;
            o0[dd] = sx * zinv0;
            o1[dd] = sy * zinv1;
        }
        float* op0 = out + ((size_t)(b * N_) + i0 + i_e) * DIN + hh * HD_ + dq * 8;
        float* op1 = op0 + DIN;
        *(float4*)&op0[0] = make_float4(o0[0], o0[1], o0[2], o0[3]);
        *(float4*)&op0[4] = make_float4(o0[4], o0[5], o0[6], o0[7]);
        *(float4*)&op1[0] = make_float4(o1[0], o1[1], o1[2], o1[3]);
        *(float4*)&op1[4] = make_float4(o1[4], o1[5], o1[6], o1[7]);
    }
}

// ---------------- launch ----------------
extern "C" void kernel_launch(void* const* d_in, const int* in_sizes, int n_in,
                              void* d_out, int out_size) {
    const float* x   = (const float*)d_in[0];
    const int*   adj = (const int*)d_in[1];
    const float* W   = (const float*)d_in[2];
    const float* a   = (const float*)d_in[3];
    float*       out = (float*)d_out;

    cudaFuncSetAttribute(k_gemm, cudaFuncAttributeMaxDynamicSharedMemorySize, GEMM_SMEM);
    cudaFuncSetAttribute(k_attn, cudaFuncAttributeMaxDynamicSharedMemorySize, ATTN_SMEM);

    k_gemm<<<B_ * N_ / 64, 256, GEMM_SMEM>>>(x, W);
    k_eij <<<B_ * N_ / 8, 256>>>(a);
    k_pack<<<(N_ * (N_ / 32) * 32) / 256, 256>>>(adj);
    k_attn<<<dim3(N_ / 128, H_, B_), 256, ATTN_SMEM>>>(out);
}